// round 13
// baseline (speedup 1.0000x reference)
#include <cuda_runtime.h>
#include <cstdint>

// SpatialPool: fm [B=16, C=512, H=38, W=38] f32 (NCHW)
//   -> out [B, H*W, 9*C] f32, out[b, h*W+w, (di*3+dj)*C + c]
//      = fm[b, c, clamp(h+di-1), clamp(w+dj-1)]  (replicate pad)
//
// R13 = R7 with row-progressive load/store overlap: the 4 halo rows are
// issued as 4 cp.async commit groups; store sub-phase r (chunks with
// o+di == r) starts as soon as row r lands (wait_group 3-r). Stores begin
// after ~1/4 of the load instead of all of it. Same smem swizzle,
// occupancy (4 CTAs/SM), and vectorized conflict-free write as R7.

namespace {
constexpr int HH   = 38;
constexpr int C    = 512;
constexpr int CSUB = 128;        // channels per CTA
constexpr int NCG  = C / CSUB;   // 4
constexpr int NB   = 9;
constexpr int WT   = 19;         // w positions per CTA
constexpr int LW   = WT + 2;     // 21 local cols incl. halo
constexpr int NY   = 2;          // output rows per CTA
constexpr int NR   = NY + 2;     // 4 loaded rows incl. halo
constexpr int NPOS = NR * LW;    // 84 smem positions
constexpr int THREADS = 512;
constexpr int HW   = HH * HH;    // 1444
constexpr int RS4  = NB * C / 4; // 1152 float4 per (b,y,w)
constexpr int YS4  = HH * RS4;   // float4 stride for y+1
}

__device__ __forceinline__ void cp_async4(float* smem_dst, const float* gsrc) {
    uint32_t sa = (uint32_t)__cvta_generic_to_shared(smem_dst);
    asm volatile("cp.async.ca.shared.global [%0], [%1], 4;\n"
                 :: "r"(sa), "l"(gsrc) : "memory");
}

__global__ __launch_bounds__(THREADS, 4)
void spatialpool_kernel(const float* __restrict__ fm, float* __restrict__ out) {
    // logical (pos, c) at smP[pos*128 + 4*((c>>2)^(pos&31)) + (c&3)]
    __shared__ float smP[NPOS * CSUB];   // 43,008 B

    const int lane = threadIdx.x & 31;
    const int wid  = threadIdx.x >> 5;

    const int wh = blockIdx.x & 1;
    const int cg = blockIdx.x >> 1;        // channel group 0..3
    const int w0 = wh * WT;
    const int y0 = blockIdx.y * NY;        // first output row
    const int b  = blockIdx.z;

    const float* __restrict__ fb =
        fm + ((size_t)b * C + (size_t)cg * CSUB) * HW;

    // ---- Load: row-major, one commit group PER ROW so consumers can
    // wait progressively. Warp w covers c = 8w..8w+7; lane -> local col
    // (lanes 0..20 active). Lanes sweep l -> coalesced 21-float runs;
    // bank = (c>>2)^(p&31) distinct per lane -> conflict-free STS. ----
    {
        const int xg = min(max(w0 - 1 + lane, 0), HH - 1);
        const float* __restrict__ fw = fb + (size_t)(8 * wid) * HW + xg;
        #pragma unroll
        for (int r = 0; r < NR; ++r) {
            if (lane < LW) {
                int p  = r * LW + lane;
                int yl = min(max(y0 - 1 + r, 0), HH - 1);
                const float* __restrict__ g = fw + yl * HH;
                const int base = (p << 7);
                const int key  = p & 31;
                #pragma unroll
                for (int j = 0; j < 8; ++j) {
                    int c = 8 * wid + j;
                    int sw = base + ((((c >> 2) ^ key) << 2) | (c & 3));
                    cp_async4(&smP[sw], g + j * HW);
                }
            }
            asm volatile("cp.async.commit_group;\n" ::: "memory");
        }
    }

    // ---- Store: sub-phase r handles chunks with o + di == r.
    // Counts per r: 57, 114, 114, 57 (total 342, each written once). ----
    float4* __restrict__ out4 = (float4*)out;
    const size_t rowbase =
        ((size_t)b * HW + (size_t)y0 * HH + w0) * (size_t)RS4
        + (size_t)cg * (CSUB / 4) + lane;

    #pragma unroll
    for (int r = 0; r < NR; ++r) {
        if (r == 0)      asm volatile("cp.async.wait_group 3;\n" ::: "memory");
        else if (r == 1) asm volatile("cp.async.wait_group 2;\n" ::: "memory");
        else if (r == 2) asm volatile("cp.async.wait_group 1;\n" ::: "memory");
        else             asm volatile("cp.async.wait_group 0;\n" ::: "memory");
        __syncthreads();

        const int olo  = (r >= 3) ? 1 : 0;       // max(0, r-2)
        const int nsub = (r == 0 || r == 3) ? 1 : 2;
        const int total = 57 * nsub;

        #pragma unroll 2
        for (int t = wid; t < total; t += THREADS / 32) {
            int s  = t;
            int o  = olo + ((s >= 57) ? 1 : 0);
            if (s >= 57) s -= 57;
            int wl = s / 3;                      // 0..18
            int dj = s - 3 * wl;
            int di = r - o;
            int n  = 3 * di + dj;
            int pos = r * LW + wl + dj;          // smem row = r

            const float4 v = *(const float4*)
                &smP[(pos << 7) + ((lane ^ (pos & 31)) << 2)];
            __stcs(&out4[rowbase + (size_t)o * YS4
                         + (size_t)wl * RS4 + n * (C / 4)], v);
        }
    }
}

extern "C" void kernel_launch(void* const* d_in, const int* in_sizes, int n_in,
                              void* d_out, int out_size) {
    const float* fm = (const float*)d_in[0];
    float* out = (float*)d_out;
    (void)in_sizes; (void)n_in; (void)out_size;

    dim3 grid(2 * NCG, HH / NY, 16);   // (8, 19, 16) = 2432 CTAs
    spatialpool_kernel<<<grid, THREADS>>>(fm, out);
}

// round 14
// speedup vs baseline: 1.2273x; 1.2273x over previous
#include <cuda_runtime.h>
#include <cstdint>

// SpatialPool: fm [B=16, C=512, H=38, W=38] f32 (NCHW)
//   -> out [B, H*W, 9*C] f32, out[b, h*W+w, (di*3+dj)*C + c]
//      = fm[b, c, clamp(h+di-1), clamp(w+dj-1)]  (replicate pad)
//
// R14 = R7 resized to 256-thread CTAs, NY=1, 7 CTAs/SM: finer cross-CTA
// load/store phase staggering per SM (7 slots instead of 4) to raise the
// store duty cycle. Load scheme and vectorized conflict-free write phase
// are R7's verbatim, just re-parameterized.

namespace {
constexpr int HH   = 38;
constexpr int C    = 512;
constexpr int CSUB = 128;        // channels per CTA
constexpr int NCG  = C / CSUB;   // 4
constexpr int NB   = 9;
constexpr int WT   = 19;         // w positions per CTA
constexpr int LW   = WT + 2;     // 21 local cols incl. halo
constexpr int NPOS = 3 * LW;     // 63 smem positions (NY=1 -> 3 rows)
constexpr int THREADS = 256;
constexpr int NWARP = THREADS / 32;   // 8
constexpr int HW   = HH * HH;    // 1444
constexpr int RS4  = NB * C / 4; // 1152 float4 per (b,y,w)
}

__device__ __forceinline__ void cp_async4(float* smem_dst, const float* gsrc) {
    uint32_t sa = (uint32_t)__cvta_generic_to_shared(smem_dst);
    asm volatile("cp.async.ca.shared.global [%0], [%1], 4;\n"
                 :: "r"(sa), "l"(gsrc) : "memory");
}

__global__ __launch_bounds__(THREADS, 7)
void spatialpool_kernel(const float* __restrict__ fm, float* __restrict__ out) {
    // logical (pos, c) at smP[pos*128 + 4*((c>>2)^(pos&31)) + (c&3)]
    __shared__ float smP[NPOS * CSUB];   // 32,256 B -> 7 CTAs/SM

    const int lane = threadIdx.x & 31;
    const int wid  = threadIdx.x >> 5;   // 0..7

    const int wh = blockIdx.x & 1;
    const int cg = blockIdx.x >> 1;      // channel group 0..3
    const int w0 = wh * WT;
    const int y  = blockIdx.y;
    const int b  = blockIdx.z;

    const float* __restrict__ fb =
        fm + ((size_t)b * C + (size_t)cg * CSUB) * HW;

    // ---- Load (R7 scheme): thread owns p = lane + 32k (k<2), sweeps
    // c = wid + 8m (m<16). Offset computed once per p; channel stride is
    // a compile-time immediate. Lanes sweep consecutive p -> coalesced. ----
    {
        const float* __restrict__ fc = fb + (size_t)wid * HW;  // c0 = wid
        const int c3  = wid & 3;
        const int cq0 = wid >> 2;
        #pragma unroll
        for (int k = 0; k < 2; ++k) {
            int p = lane + 32 * k;
            if (k == 1 && p >= NPOS) break;
            int r  = p / LW;
            int l  = p - r * LW;
            int yl = min(max(y - 1 + r, 0), HH - 1);
            int xg = min(max(w0 - 1 + l, 0), HH - 1);
            const float* __restrict__ g = fc + yl * HH + xg;
            const int swk = (p << 7) + c3;
            #pragma unroll
            for (int m = 0; m < 16; ++m) {
                int sw = swk + (((cq0 + 2 * m) ^ lane) << 2);
                cp_async4(&smP[sw], g + m * 8 * HW);
            }
        }
    }
    asm volatile("cp.async.wait_all;\n" ::: "memory");
    __syncthreads();

    // ---- Write (R7 scheme): n-major warp-per-chunk; one conflict-free
    // LDS.128 + one coalesced 512B STG.128.cs per chunk. ----
    float4* __restrict__ out4 = (float4*)out;
    const size_t rowbase =
        ((size_t)b * HW + (size_t)y * HH + w0) * (size_t)RS4
        + (size_t)cg * (CSUB / 4) + lane;

    #pragma unroll
    for (int n = 0; n < NB; ++n) {
        const int di = n / 3;
        const int dj = n - di * 3;
        #pragma unroll 3
        for (int wl = wid; wl < WT; wl += NWARP) {
            int pos = di * LW + wl + dj;

            const float4 v = *(const float4*)
                &smP[(pos << 7) + ((lane ^ (pos & 31)) << 2)];
            __stcs(&out4[rowbase + (size_t)wl * RS4 + n * (C / 4)], v);
        }
    }
}

extern "C" void kernel_launch(void* const* d_in, const int* in_sizes, int n_in,
                              void* d_out, int out_size) {
    const float* fm = (const float*)d_in[0];
    float* out = (float*)d_out;
    (void)in_sizes; (void)n_in; (void)out_size;

    dim3 grid(2 * NCG, HH, 16);   // (8, 38, 16) = 4864 CTAs
    spatialpool_kernel<<<grid, THREADS>>>(fm, out);
}